// round 13
// baseline (speedup 1.0000x reference)
#include <cuda_runtime.h>
#include <cuda_bf16.h>
#include <cstdint>

#define TT   4096
#define HH   2048
#define DIN  12325
#define DBLK 2054

// ======================= scratch (__device__ globals, no cudaMalloc) =======================
__device__ __nv_bfloat16 g_act_hi[2][2][(size_t)TT * HH];
__device__ __nv_bfloat16 g_act_lo[2][2][(size_t)TT * HH];
__device__ __nv_bfloat16 g_w_hi[2][2][(size_t)HH * HH];
__device__ __nv_bfloat16 g_w_lo[2][2][(size_t)HH * HH];
__device__ float g_c[2][HH];
__device__ float g_u[2][5][HH];
__device__ float g_wl[2][HH];
__device__ float g_D[2][6][HH];

// ======================= helpers =======================
__device__ __forceinline__ uint32_t smem_u32(const void* p) {
    uint32_t a;
    asm("{ .reg .u64 t; cvta.to.shared.u64 t, %1; cvt.u32.u64 %0, t; }" : "=r"(a) : "l"(p));
    return a;
}
__device__ __forceinline__ void cp16(uint32_t s, const void* g) {
    asm volatile("cp.async.cg.shared.global [%0], [%1], 16;" :: "r"(s), "l"(g));
}
#define MBAR_INIT(mb, c)   asm volatile("mbarrier.init.shared.b64 [%0], %1;" :: "r"(mb), "r"(c) : "memory")
#define MBAR_ARRIVE(mb)    asm volatile("mbarrier.arrive.shared.b64 _, [%0];" :: "r"(mb) : "memory")
#define CP_MBAR_ARRIVE(mb) asm volatile("cp.async.mbarrier.arrive.noinc.shared.b64 [%0];" :: "r"(mb) : "memory")

#define MBAR_WAIT_PARITY(mbar_smem_addr, phase_parity) do {                                  \
    uint32_t _mbar = (uint32_t)(mbar_smem_addr);                                             \
    uint32_t _parity = (uint32_t)(phase_parity);                                             \
    uint32_t _done;                                                                          \
    asm volatile(                                                                            \
        "{\n\t.reg .pred p;\n\t"                                                             \
        "mbarrier.try_wait.parity.acquire.cta.shared::cta.b64 p, [%1], %2;\n\t"              \
        "selp.b32 %0, 1, 0, p;\n\t}"                                                         \
        : "=r"(_done) : "r"(_mbar), "r"(_parity) : "memory");                                \
    if (!_done) {                                                                            \
        asm volatile(                                                                        \
            "{\n\t.reg .pred P1;\n\t"                                                        \
            "WAIT_LOOP_%=:\n\t"                                                              \
            "mbarrier.try_wait.parity.acquire.cta.shared::cta.b64 P1, [%0], %1, 0x989680;\n\t" \
            "@P1 bra.uni WAIT_DONE_%=;\n\t"                                                  \
            "bra.uni WAIT_LOOP_%=;\n\t"                                                      \
            "WAIT_DONE_%=:\n\t}"                                                             \
            :: "r"(_mbar), "r"(_parity) : "memory");                                         \
    }                                                                                        \
} while (0)

__device__ __forceinline__ void ldsm4(uint32_t* r, uint32_t addr) {
    asm volatile("ldmatrix.sync.aligned.m8n8.x4.shared.b16 {%0,%1,%2,%3}, [%4];"
                 : "=r"(r[0]), "=r"(r[1]), "=r"(r[2]), "=r"(r[3]) : "r"(addr));
}
__device__ __forceinline__ void ldsm2(uint32_t* r, uint32_t addr) {
    asm volatile("ldmatrix.sync.aligned.m8n8.x2.shared.b16 {%0,%1}, [%2];"
                 : "=r"(r[0]), "=r"(r[1]) : "r"(addr));
}
__device__ __forceinline__ void mma16816(float* c, const uint32_t* a, const uint32_t* b) {
    asm volatile("mma.sync.aligned.m16n8k16.row.col.f32.bf16.bf16.f32 "
                 "{%0,%1,%2,%3}, {%4,%5,%6,%7}, {%8,%9}, {%0,%1,%2,%3};"
                 : "+f"(c[0]), "+f"(c[1]), "+f"(c[2]), "+f"(c[3])
                 : "r"(a[0]), "r"(a[1]), "r"(a[2]), "r"(a[3]), "r"(b[0]), "r"(b[1]));
}
__device__ __forceinline__ float gelu_f(float x) {
    return 0.5f * x * (1.0f + erff(x * 0.7071067811865476f));
}
__device__ __forceinline__ uint32_t pk2(float a, float b) {
    __nv_bfloat162 t = __floats2bfloat162_rn(a, b);
    return reinterpret_cast<uint32_t&>(t);
}
__device__ __forceinline__ uint32_t sw128(uint32_t off) {
    return off ^ ((off >> 3) & 0x70u);
}

// ======================= kernel 1: split H x H weights into bf16 hi/lo (float4) =======================
__global__ void wsplit_kernel(const float* __restrict__ Wf1, const float* __restrict__ Wf2,
                              const float* __restrict__ Wb1, const float* __restrict__ Wb2) {
    size_t idx = (size_t)blockIdx.x * 256 + threadIdx.x;   // 4 * 2^20 float4 chunks
    int w = (int)(idx >> 20);
    size_t e4 = idx & ((1u << 20) - 1u);
    const float* src = (w == 0) ? Wf1 : (w == 1) ? Wf2 : (w == 2) ? Wb1 : Wb2;
    float4 v = *(const float4*)(src + e4 * 4);
    float h0 = __bfloat162float(__float2bfloat16_rn(v.x));
    float h1 = __bfloat162float(__float2bfloat16_rn(v.y));
    float h2 = __bfloat162float(__float2bfloat16_rn(v.z));
    float h3 = __bfloat162float(__float2bfloat16_rn(v.w));
    uint2 hv, lv;
    hv.x = pk2(h0, h1); hv.y = pk2(h2, h3);
    lv.x = pk2(v.x - h0, v.y - h1); lv.y = pk2(v.z - h2, v.w - h3);
    *(uint2*)(g_w_hi[w >> 1][w & 1] + e4 * 4) = hv;
    *(uint2*)(g_w_lo[w >> 1][w & 1] + e4 * 4) = lv;
}

// ======================= kernel 2: layer-0 decomposition (one pass over W0) =======================
__global__ void precompute_kernel(const float* __restrict__ Wf0, const float* __restrict__ Wb0,
                                  const float* __restrict__ bf0, const float* __restrict__ bb0,
                                  const float* __restrict__ mol, const float* __restrict__ sv) {
    __shared__ float red[256];
    int h = blockIdx.x, z = blockIdx.y, tid = threadIdx.x;
    const float* W0 = z ? Wb0 : Wf0;
    const float* row = W0 + (size_t)h * DIN;
    float acc[6] = {0.f, 0.f, 0.f, 0.f, 0.f, 0.f};
    for (int m = tid; m < 2048; m += 256) {
        acc[0] += row[m] * mol[m];
#pragma unroll
        for (int j = 0; j < 5; j++)
            acc[1 + j] += row[DBLK * (j + 1) + m] * sv[j * 2048 + m];
    }
#pragma unroll
    for (int a = 0; a < 6; a++) {
        red[tid] = acc[a];
        __syncthreads();
        for (int s = 128; s > 0; s >>= 1) {
            if (tid < s) red[tid] += red[tid + s];
            __syncthreads();
        }
        if (tid == 0) {
            if (a == 0) g_c[z][h] = red[0] + (z ? bb0[h] : bf0[h]);
            else        g_u[z][a - 1][h] = red[0];
        }
        __syncthreads();
    }
    if (tid < 6) {
        float dsum = row[2048 + tid];
#pragma unroll
        for (int j = 0; j < 5; j++) dsum += row[DBLK * (j + 1) + 2048 + tid];
        g_D[z][tid][h] = dsum;
    }
    if (tid == 6) g_wl[z][h] = row[12324];
}

// ======================= kernel 3: layer-0 activation (12 FMA/elem broadcast) =======================
__global__ void act0_kernel(const float* __restrict__ sseq, const float* __restrict__ dseq,
                            const float* __restrict__ rf) {
    int h = blockIdx.x * 256 + threadIdx.x;
    int t = blockIdx.y, z = blockIdx.z;
    float pv = (z == 0) ? ((t == 0) ? 0.5f : rf[t - 1])
                        : ((t == TT - 1) ? 0.5f : rf[t + 1]);
    float v = g_c[z][h] + pv * g_wl[z][h];
#pragma unroll
    for (int j = 0; j < 5; j++) v += __ldg(&sseq[t * 5 + j]) * g_u[z][j][h];
#pragma unroll
    for (int d = 0; d < 6; d++) v += __ldg(&dseq[t * 6 + d]) * g_D[z][d][h];
    float g = gelu_f(v);
    __nv_bfloat16 hi = __float2bfloat16_rn(g);
    __nv_bfloat16 lo = __float2bfloat16_rn(g - __bfloat162float(hi));
    size_t idx = (size_t)t * HH + h;
    g_act_hi[z][0][idx] = hi;
    g_act_lo[z][0][idx] = lo;
}

// ======================= kernel 4: mma.sync split-bf16 GEMM, mbarrier ring pipeline ==========
// CTA tile 128(t) x 128(n), BK=64, 8 warps as 2x4 grid of 64x32 warp tiles.
// 3 HMMA products per k16-step. 3 x 64KB buffers; per-buffer full/free mbarriers;
// no __syncthreads in the mainloop -> warps decouple (skew tolerance ~1 stage).
#define SA_HI 0
#define SA_LO 16384
#define SW_HI 32768
#define SW_LO 49152
#define STAGE_B 65536
#define NSTAGE  3
#define GEMM_SMEM (NSTAGE * STAGE_B + 1024)

__global__ void __launch_bounds__(256, 1)
gemm_kernel(int layer, const float* __restrict__ bias_f, const float* __restrict__ bias_b) {
    extern __shared__ char smem[];
    const uint32_t sbase = smem_u32(smem);
    const uint32_t s0 = (sbase + 1023u) & ~1023u;
    const uint32_t mb_full = s0 + NSTAGE * STAGE_B;      // full[0..2] @ +0,+8,+16
    const uint32_t mb_free = mb_full + 24;               // free[0..2] @ +0,+8,+16

    const int tid = threadIdx.x, lane = tid & 31, warp = tid >> 5;
    const int wm = warp >> 2, wn = warp & 3;          // 2 x 4 warp grid, tile 64x32
    const int n0 = blockIdx.x * 128, t0 = blockIdx.y * 128, z = blockIdx.z;
    const int inp = layer, outp = layer ^ 1;

    const char* Ahi = (const char*)g_act_hi[z][inp];
    const char* Alo = (const char*)g_act_lo[z][inp];
    const char* Whi = (const char*)g_w_hi[z][layer];
    const char* Wlo = (const char*)g_w_lo[z][layer];
    const float* __restrict__ bias = z ? bias_b : bias_f;

    if (tid == 0) {
#pragma unroll
        for (int b = 0; b < NSTAGE; b++) {
            MBAR_INIT(mb_full + b * 8, 256);
            MBAR_INIT(mb_free + b * 8, 256);
        }
    }
    __syncthreads();   // mbarrier init visible before any arrive

    const int lr = tid >> 3, lc = tid & 7;            // loaders: 32 rows x 8 x 16B chunks

    auto load_stage = [&](int kc, int buf) {
        const uint32_t sb = s0 + (uint32_t)buf * STAGE_B;
        const int kb = kc * 128 + lc * 16;            // byte offset within 4096B K-row
#pragma unroll
        for (int p = 0; p < 4; p++) {
            const int r = p * 32 + lr;
            const uint32_t sw = sw128((uint32_t)(r * 128 + lc * 16));
            const size_t ga = (size_t)(t0 + r) * 4096 + kb;
            const size_t gw = (size_t)(n0 + r) * 4096 + kb;
            cp16(sb + SA_HI + sw, Ahi + ga);
            cp16(sb + SA_LO + sw, Alo + ga);
            cp16(sb + SW_HI + sw, Whi + gw);
            cp16(sb + SW_LO + sw, Wlo + gw);
        }
    };

    float acc[4][4][4];
#pragma unroll
    for (int i = 0; i < 4; i++)
#pragma unroll
        for (int j = 0; j < 4; j++)
#pragma unroll
            for (int q = 0; q < 4; q++) acc[i][j][q] = 0.f;

    // preload stages 0, 1 (buffers fresh: no free-wait)
    load_stage(0, 0); CP_MBAR_ARRIVE(mb_full + 0);
    load_stage(1, 1); CP_MBAR_ARRIVE(mb_full + 8);

    int cbuf = 0, cph = 0;        // consumer cursor (full)
    int pbuf = 2, pph = 1;        // producer cursor (free); parity 1 passes immediately on fresh barrier

    for (int kc = 0; kc < 32; ++kc) {
        MBAR_WAIT_PARITY(mb_full + cbuf * 8, cph);    // acquire: stage kc data visible
        const uint32_t sb = s0 + (uint32_t)cbuf * STAGE_B;

#pragma unroll
        for (int ks = 0; ks < 4; ks++) {
            const int acol = ks * 32 + (lane >> 4) * 16;          // A k-bytes
            const int bcol = ks * 32 + ((lane >> 3) & 1) * 16;    // B k-bytes
            uint32_t ah[4][4], bh[4][2], bl[4][2];
#pragma unroll
            for (int i = 0; i < 4; i++) {
                const int row = wm * 64 + i * 16 + (lane & 15);
                ldsm4(ah[i], sb + SA_HI + sw128((uint32_t)(row * 128 + acol)));
            }
#pragma unroll
            for (int j = 0; j < 4; j++) {
                const int row = wn * 32 + j * 8 + (lane & 7);
                const uint32_t sw = sw128((uint32_t)(row * 128 + bcol));
                ldsm2(bh[j], sb + SW_HI + sw);
                ldsm2(bl[j], sb + SW_LO + sw);
            }
#pragma unroll
            for (int i = 0; i < 4; i++)
#pragma unroll
                for (int j = 0; j < 4; j++) mma16816(acc[i][j], ah[i], bh[j]);
#pragma unroll
            for (int i = 0; i < 4; i++)
#pragma unroll
                for (int j = 0; j < 4; j++) mma16816(acc[i][j], ah[i], bl[j]);
            uint32_t al[4][4];
#pragma unroll
            for (int i = 0; i < 4; i++) {
                const int row = wm * 64 + i * 16 + (lane & 15);
                ldsm4(al[i], sb + SA_LO + sw128((uint32_t)(row * 128 + acol)));
            }
            if (ks == 3) MBAR_ARRIVE(mb_free + cbuf * 8);   // last smem read done; release buffer
#pragma unroll
            for (int i = 0; i < 4; i++)
#pragma unroll
                for (int j = 0; j < 4; j++) mma16816(acc[i][j], al[i], bh[j]);
        }
        if (++cbuf == NSTAGE) { cbuf = 0; cph ^= 1; }

        const int s = kc + 2;
        if (s < 32) {
            MBAR_WAIT_PARITY(mb_free + pbuf * 8, pph);      // wait consumers of stage s-3
            load_stage(s, pbuf);
            CP_MBAR_ARRIVE(mb_full + pbuf * 8);
            if (++pbuf == NSTAGE) { pbuf = 0; pph ^= 1; }
        }
    }

    // epilogue: bias + GELU + hi/lo split
    __nv_bfloat16* Oh = g_act_hi[z][outp];
    __nv_bfloat16* Ol = g_act_lo[z][outp];
#pragma unroll
    for (int i = 0; i < 4; i++) {
#pragma unroll
        for (int j = 0; j < 4; j++) {
            const int r0 = t0 + wm * 64 + i * 16 + (lane >> 2);
            const int c  = n0 + wn * 32 + j * 8 + (lane & 3) * 2;
            const float b0 = __ldg(&bias[c]), b1 = __ldg(&bias[c + 1]);
#pragma unroll
            for (int hrow = 0; hrow < 2; hrow++) {
                const float v0 = acc[i][j][hrow * 2 + 0] + b0;
                const float v1 = acc[i][j][hrow * 2 + 1] + b1;
                const float g0 = gelu_f(v0), g1 = gelu_f(v1);
                const float h0 = __bfloat162float(__float2bfloat16_rn(g0));
                const float h1 = __bfloat162float(__float2bfloat16_rn(g1));
                const size_t o = (size_t)(r0 + hrow * 8) * HH + c;
                *(uint32_t*)(Oh + o) = pk2(h0, h1);
                *(uint32_t*)(Ol + o) = pk2(g0 - h0, g1 - h1);
            }
        }
    }
}

// ======================= kernel 5: output head (GEMV + clip) =======================
__global__ void head_kernel(const float* __restrict__ Wof, const float* __restrict__ Wob,
                            const float* __restrict__ bof, const float* __restrict__ bob,
                            float* __restrict__ out) {
    int t = blockIdx.x, z = blockIdx.y, tid = threadIdx.x;
    const float* Wo = z ? Wob : Wof;
    const __nv_bfloat16* hi = g_act_hi[z][0] + (size_t)t * HH;
    const __nv_bfloat16* lo = g_act_lo[z][0] + (size_t)t * HH;
    float acc = 0.f;
    for (int n = tid; n < HH; n += 128)
        acc += (__bfloat162float(hi[n]) + __bfloat162float(lo[n])) * Wo[n];
    for (int o = 16; o; o >>= 1) acc += __shfl_down_sync(0xffffffffu, acc, o);
    __shared__ float red[4];
    if ((tid & 31) == 0) red[tid >> 5] = acc;
    __syncthreads();
    if (tid == 0) {
        float v = red[0] + red[1] + red[2] + red[3] + (z ? bob[0] : bof[0]);
        v = fminf(fmaxf(v, 1e-4f), 1.0f - 1e-4f);
        out[(size_t)z * TT + t] = v;
    }
}

// ======================= launch =======================
extern "C" void kernel_launch(void* const* d_in, const int* in_sizes, int n_in,
                              void* d_out, int out_size) {
    (void)in_sizes; (void)n_in; (void)out_size;
    const float* mol  = (const float*)d_in[0];
    const float* sseq = (const float*)d_in[1];
    const float* dseq = (const float*)d_in[2];
    const float* rf   = (const float*)d_in[3];
    const float* sv   = (const float*)d_in[4];
    const float* Wf0 = (const float*)d_in[5],  *Wf1 = (const float*)d_in[6];
    const float* Wf2 = (const float*)d_in[7],  *Wof = (const float*)d_in[8];
    const float* Wb0 = (const float*)d_in[9],  *Wb1 = (const float*)d_in[10];
    const float* Wb2 = (const float*)d_in[11], *Wob = (const float*)d_in[12];
    const float* bf0 = (const float*)d_in[13], *bf1 = (const float*)d_in[14];
    const float* bf2 = (const float*)d_in[15], *bof = (const float*)d_in[16];
    const float* bb0 = (const float*)d_in[17], *bb1 = (const float*)d_in[18];
    const float* bb2 = (const float*)d_in[19], *bob = (const float*)d_in[20];
    float* out = (float*)d_out;

    cudaFuncSetAttribute(gemm_kernel, cudaFuncAttributeMaxDynamicSharedMemorySize, GEMM_SMEM);

    wsplit_kernel<<<16384, 256>>>(Wf1, Wf2, Wb1, Wb2);
    precompute_kernel<<<dim3(HH, 2), 256>>>(Wf0, Wb0, bf0, bb0, mol, sv);
    act0_kernel<<<dim3(HH / 256, TT, 2), 256>>>(sseq, dseq, rf);
    gemm_kernel<<<dim3(HH / 128, TT / 128, 2), 256, GEMM_SMEM>>>(0, bf1, bb1);
    gemm_kernel<<<dim3(HH / 128, TT / 128, 2), 256, GEMM_SMEM>>>(1, bf2, bb2);
    head_kernel<<<dim3(TT, 2), 128>>>(Wof, Wob, bof, bob, out);
}

// round 14
// speedup vs baseline: 1.0077x; 1.0077x over previous
#include <cuda_runtime.h>
#include <cuda_bf16.h>
#include <cstdint>

#define TT   4096
#define HH   2048
#define DIN  12325
#define DBLK 2054

// ======================= scratch (__device__ globals, no cudaMalloc) =======================
__device__ __nv_bfloat16 g_act_hi[2][2][(size_t)TT * HH];
__device__ __nv_bfloat16 g_act_lo[2][2][(size_t)TT * HH];
__device__ __nv_bfloat16 g_w_hi[2][2][(size_t)HH * HH];
__device__ __nv_bfloat16 g_w_lo[2][2][(size_t)HH * HH];
__device__ float g_c[2][HH];
__device__ float g_u[2][5][HH];
__device__ float g_wl[2][HH];
__device__ float g_D[2][6][HH];

// ======================= helpers =======================
__device__ __forceinline__ uint32_t smem_u32(const void* p) {
    uint32_t a;
    asm("{ .reg .u64 t; cvta.to.shared.u64 t, %1; cvt.u32.u64 %0, t; }" : "=r"(a) : "l"(p));
    return a;
}
__device__ __forceinline__ void cp16(uint32_t s, const void* g) {
    asm volatile("cp.async.cg.shared.global [%0], [%1], 16;" :: "r"(s), "l"(g));
}
#define MBAR_INIT(mb, c)   asm volatile("mbarrier.init.shared.b64 [%0], %1;" :: "r"(mb), "r"(c) : "memory")
#define MBAR_ARRIVE(mb)    asm volatile("mbarrier.arrive.shared.b64 _, [%0];" :: "r"(mb) : "memory")
#define CP_MBAR_ARRIVE(mb) asm volatile("cp.async.mbarrier.arrive.noinc.shared.b64 [%0];" :: "r"(mb) : "memory")

#define MBAR_WAIT_PARITY(mbar_smem_addr, phase_parity) do {                                  \
    uint32_t _mbar = (uint32_t)(mbar_smem_addr);                                             \
    uint32_t _parity = (uint32_t)(phase_parity);                                             \
    uint32_t _done;                                                                          \
    asm volatile(                                                                            \
        "{\n\t.reg .pred p;\n\t"                                                             \
        "mbarrier.try_wait.parity.acquire.cta.shared::cta.b64 p, [%1], %2;\n\t"              \
        "selp.b32 %0, 1, 0, p;\n\t}"                                                         \
        : "=r"(_done) : "r"(_mbar), "r"(_parity) : "memory");                                \
    if (!_done) {                                                                            \
        asm volatile(                                                                        \
            "{\n\t.reg .pred P1;\n\t"                                                        \
            "WAIT_LOOP_%=:\n\t"                                                              \
            "mbarrier.try_wait.parity.acquire.cta.shared::cta.b64 P1, [%0], %1, 0x989680;\n\t" \
            "@P1 bra.uni WAIT_DONE_%=;\n\t"                                                  \
            "bra.uni WAIT_LOOP_%=;\n\t"                                                      \
            "WAIT_DONE_%=:\n\t}"                                                             \
            :: "r"(_mbar), "r"(_parity) : "memory");                                         \
    }                                                                                        \
} while (0)

__device__ __forceinline__ void ldsm4(uint32_t* r, uint32_t addr) {
    asm volatile("ldmatrix.sync.aligned.m8n8.x4.shared.b16 {%0,%1,%2,%3}, [%4];"
                 : "=r"(r[0]), "=r"(r[1]), "=r"(r[2]), "=r"(r[3]) : "r"(addr));
}
__device__ __forceinline__ void ldsm2(uint32_t* r, uint32_t addr) {
    asm volatile("ldmatrix.sync.aligned.m8n8.x2.shared.b16 {%0,%1}, [%2];"
                 : "=r"(r[0]), "=r"(r[1]) : "r"(addr));
}
__device__ __forceinline__ void mma16816(float* c, const uint32_t* a, const uint32_t* b) {
    asm volatile("mma.sync.aligned.m16n8k16.row.col.f32.bf16.bf16.f32 "
                 "{%0,%1,%2,%3}, {%4,%5,%6,%7}, {%8,%9}, {%0,%1,%2,%3};"
                 : "+f"(c[0]), "+f"(c[1]), "+f"(c[2]), "+f"(c[3])
                 : "r"(a[0]), "r"(a[1]), "r"(a[2]), "r"(a[3]), "r"(b[0]), "r"(b[1]));
}
__device__ __forceinline__ float gelu_f(float x) {
    return 0.5f * x * (1.0f + erff(x * 0.7071067811865476f));
}
__device__ __forceinline__ uint32_t pk2(float a, float b) {
    __nv_bfloat162 t = __floats2bfloat162_rn(a, b);
    return reinterpret_cast<uint32_t&>(t);
}
__device__ __forceinline__ uint32_t sw128(uint32_t off) {
    return off ^ ((off >> 3) & 0x70u);
}

// ======================= kernel 1: split H x H weights into bf16 hi/lo (float4) =======================
__global__ void wsplit_kernel(const float* __restrict__ Wf1, const float* __restrict__ Wf2,
                              const float* __restrict__ Wb1, const float* __restrict__ Wb2) {
    size_t idx = (size_t)blockIdx.x * 256 + threadIdx.x;   // 4 * 2^20 float4 chunks
    int w = (int)(idx >> 20);
    size_t e4 = idx & ((1u << 20) - 1u);
    const float* src = (w == 0) ? Wf1 : (w == 1) ? Wf2 : (w == 2) ? Wb1 : Wb2;
    float4 v = *(const float4*)(src + e4 * 4);
    float h0 = __bfloat162float(__float2bfloat16_rn(v.x));
    float h1 = __bfloat162float(__float2bfloat16_rn(v.y));
    float h2 = __bfloat162float(__float2bfloat16_rn(v.z));
    float h3 = __bfloat162float(__float2bfloat16_rn(v.w));
    uint2 hv, lv;
    hv.x = pk2(h0, h1); hv.y = pk2(h2, h3);
    lv.x = pk2(v.x - h0, v.y - h1); lv.y = pk2(v.z - h2, v.w - h3);
    *(uint2*)(g_w_hi[w >> 1][w & 1] + e4 * 4) = hv;
    *(uint2*)(g_w_lo[w >> 1][w & 1] + e4 * 4) = lv;
}

// ======================= kernel 2: layer-0 decomposition (one pass over W0) =======================
__global__ void precompute_kernel(const float* __restrict__ Wf0, const float* __restrict__ Wb0,
                                  const float* __restrict__ bf0, const float* __restrict__ bb0,
                                  const float* __restrict__ mol, const float* __restrict__ sv) {
    __shared__ float red[256];
    int h = blockIdx.x, z = blockIdx.y, tid = threadIdx.x;
    const float* W0 = z ? Wb0 : Wf0;
    const float* row = W0 + (size_t)h * DIN;
    float acc[6] = {0.f, 0.f, 0.f, 0.f, 0.f, 0.f};
    for (int m = tid; m < 2048; m += 256) {
        acc[0] += row[m] * mol[m];
#pragma unroll
        for (int j = 0; j < 5; j++)
            acc[1 + j] += row[DBLK * (j + 1) + m] * sv[j * 2048 + m];
    }
#pragma unroll
    for (int a = 0; a < 6; a++) {
        red[tid] = acc[a];
        __syncthreads();
        for (int s = 128; s > 0; s >>= 1) {
            if (tid < s) red[tid] += red[tid + s];
            __syncthreads();
        }
        if (tid == 0) {
            if (a == 0) g_c[z][h] = red[0] + (z ? bb0[h] : bf0[h]);
            else        g_u[z][a - 1][h] = red[0];
        }
        __syncthreads();
    }
    if (tid < 6) {
        float dsum = row[2048 + tid];
#pragma unroll
        for (int j = 0; j < 5; j++) dsum += row[DBLK * (j + 1) + 2048 + tid];
        g_D[z][tid][h] = dsum;
    }
    if (tid == 6) g_wl[z][h] = row[12324];
}

// ======================= kernel 3: layer-0 activation (12 FMA/elem broadcast) =======================
__global__ void act0_kernel(const float* __restrict__ sseq, const float* __restrict__ dseq,
                            const float* __restrict__ rf) {
    int h = blockIdx.x * 256 + threadIdx.x;
    int t = blockIdx.y, z = blockIdx.z;
    float pv = (z == 0) ? ((t == 0) ? 0.5f : rf[t - 1])
                        : ((t == TT - 1) ? 0.5f : rf[t + 1]);
    float v = g_c[z][h] + pv * g_wl[z][h];
#pragma unroll
    for (int j = 0; j < 5; j++) v += __ldg(&sseq[t * 5 + j]) * g_u[z][j][h];
#pragma unroll
    for (int d = 0; d < 6; d++) v += __ldg(&dseq[t * 6 + d]) * g_D[z][d][h];
    float g = gelu_f(v);
    __nv_bfloat16 hi = __float2bfloat16_rn(g);
    __nv_bfloat16 lo = __float2bfloat16_rn(g - __bfloat162float(hi));
    size_t idx = (size_t)t * HH + h;
    g_act_hi[z][0][idx] = hi;
    g_act_lo[z][0][idx] = lo;
}

// ======================= kernel 4: mma.sync split-bf16 GEMM, mbarrier ring pipeline ==========
// CTA tile 128(t) x 128(n), BK=64, 8 warps as 2x4 grid of 64x32 warp tiles.
// 3 HMMA products per k16-step. 3 x 64KB buffers; per-buffer full/free mbarriers;
// no __syncthreads in the mainloop -> warps decouple (skew tolerance ~1 stage).
#define SA_HI 0
#define SA_LO 16384
#define SW_HI 32768
#define SW_LO 49152
#define STAGE_B 65536
#define NSTAGE  3
#define GEMM_SMEM (NSTAGE * STAGE_B + 1024)

__global__ void __launch_bounds__(256, 1)
gemm_kernel(int layer, const float* __restrict__ bias_f, const float* __restrict__ bias_b) {
    extern __shared__ char smem[];
    const uint32_t sbase = smem_u32(smem);
    const uint32_t s0 = (sbase + 1023u) & ~1023u;
    const uint32_t mb_full = s0 + NSTAGE * STAGE_B;      // full[0..2] @ +0,+8,+16
    const uint32_t mb_free = mb_full + 24;               // free[0..2] @ +0,+8,+16

    const int tid = threadIdx.x, lane = tid & 31, warp = tid >> 5;
    const int wm = warp >> 2, wn = warp & 3;          // 2 x 4 warp grid, tile 64x32
    const int n0 = blockIdx.x * 128, t0 = blockIdx.y * 128, z = blockIdx.z;
    const int inp = layer, outp = layer ^ 1;

    const char* Ahi = (const char*)g_act_hi[z][inp];
    const char* Alo = (const char*)g_act_lo[z][inp];
    const char* Whi = (const char*)g_w_hi[z][layer];
    const char* Wlo = (const char*)g_w_lo[z][layer];
    const float* __restrict__ bias = z ? bias_b : bias_f;

    if (tid == 0) {
#pragma unroll
        for (int b = 0; b < NSTAGE; b++) {
            MBAR_INIT(mb_full + b * 8, 256);
            MBAR_INIT(mb_free + b * 8, 256);
        }
    }
    __syncthreads();   // mbarrier init visible before any arrive

    const int lr = tid >> 3, lc = tid & 7;            // loaders: 32 rows x 8 x 16B chunks

    auto load_stage = [&](int kc, int buf) {
        const uint32_t sb = s0 + (uint32_t)buf * STAGE_B;
        const int kb = kc * 128 + lc * 16;            // byte offset within 4096B K-row
#pragma unroll
        for (int p = 0; p < 4; p++) {
            const int r = p * 32 + lr;
            const uint32_t sw = sw128((uint32_t)(r * 128 + lc * 16));
            const size_t ga = (size_t)(t0 + r) * 4096 + kb;
            const size_t gw = (size_t)(n0 + r) * 4096 + kb;
            cp16(sb + SA_HI + sw, Ahi + ga);
            cp16(sb + SA_LO + sw, Alo + ga);
            cp16(sb + SW_HI + sw, Whi + gw);
            cp16(sb + SW_LO + sw, Wlo + gw);
        }
    };

    float acc[4][4][4];
#pragma unroll
    for (int i = 0; i < 4; i++)
#pragma unroll
        for (int j = 0; j < 4; j++)
#pragma unroll
            for (int q = 0; q < 4; q++) acc[i][j][q] = 0.f;

    // preload stages 0, 1 (buffers fresh: no free-wait)
    load_stage(0, 0); CP_MBAR_ARRIVE(mb_full + 0);
    load_stage(1, 1); CP_MBAR_ARRIVE(mb_full + 8);

    int cbuf = 0, cph = 0;        // consumer cursor (full)
    int pbuf = 2, pph = 1;        // producer cursor (free); parity 1 passes immediately on fresh barrier

    for (int kc = 0; kc < 32; ++kc) {
        MBAR_WAIT_PARITY(mb_full + cbuf * 8, cph);    // acquire: stage kc data visible
        const uint32_t sb = s0 + (uint32_t)cbuf * STAGE_B;

#pragma unroll
        for (int ks = 0; ks < 4; ks++) {
            const int acol = ks * 32 + (lane >> 4) * 16;          // A k-bytes
            const int bcol = ks * 32 + ((lane >> 3) & 1) * 16;    // B k-bytes
            uint32_t ah[4][4], bh[4][2], bl[4][2];
#pragma unroll
            for (int i = 0; i < 4; i++) {
                const int row = wm * 64 + i * 16 + (lane & 15);
                ldsm4(ah[i], sb + SA_HI + sw128((uint32_t)(row * 128 + acol)));
            }
#pragma unroll
            for (int j = 0; j < 4; j++) {
                const int row = wn * 32 + j * 8 + (lane & 7);
                const uint32_t sw = sw128((uint32_t)(row * 128 + bcol));
                ldsm2(bh[j], sb + SW_HI + sw);
                ldsm2(bl[j], sb + SW_LO + sw);
            }
#pragma unroll
            for (int i = 0; i < 4; i++)
#pragma unroll
                for (int j = 0; j < 4; j++) mma16816(acc[i][j], ah[i], bh[j]);
#pragma unroll
            for (int i = 0; i < 4; i++)
#pragma unroll
                for (int j = 0; j < 4; j++) mma16816(acc[i][j], ah[i], bl[j]);
            uint32_t al[4][4];
#pragma unroll
            for (int i = 0; i < 4; i++) {
                const int row = wm * 64 + i * 16 + (lane & 15);
                ldsm4(al[i], sb + SA_LO + sw128((uint32_t)(row * 128 + acol)));
            }
            if (ks == 3) MBAR_ARRIVE(mb_free + cbuf * 8);   // last smem read done; release buffer
#pragma unroll
            for (int i = 0; i < 4; i++)
#pragma unroll
                for (int j = 0; j < 4; j++) mma16816(acc[i][j], al[i], bh[j]);
        }
        if (++cbuf == NSTAGE) { cbuf = 0; cph ^= 1; }

        const int s = kc + 2;
        if (s < 32) {
            MBAR_WAIT_PARITY(mb_free + pbuf * 8, pph);      // wait consumers of stage s-3
            load_stage(s, pbuf);
            CP_MBAR_ARRIVE(mb_full + pbuf * 8);
            if (++pbuf == NSTAGE) { pbuf = 0; pph ^= 1; }
        }
    }

    // epilogue: bias + GELU + hi/lo split
    __nv_bfloat16* Oh = g_act_hi[z][outp];
    __nv_bfloat16* Ol = g_act_lo[z][outp];
#pragma unroll
    for (int i = 0; i < 4; i++) {
#pragma unroll
        for (int j = 0; j < 4; j++) {
            const int r0 = t0 + wm * 64 + i * 16 + (lane >> 2);
            const int c  = n0 + wn * 32 + j * 8 + (lane & 3) * 2;
            const float b0 = __ldg(&bias[c]), b1 = __ldg(&bias[c + 1]);
#pragma unroll
            for (int hrow = 0; hrow < 2; hrow++) {
                const float v0 = acc[i][j][hrow * 2 + 0] + b0;
                const float v1 = acc[i][j][hrow * 2 + 1] + b1;
                const float g0 = gelu_f(v0), g1 = gelu_f(v1);
                const float h0 = __bfloat162float(__float2bfloat16_rn(g0));
                const float h1 = __bfloat162float(__float2bfloat16_rn(g1));
                const size_t o = (size_t)(r0 + hrow * 8) * HH + c;
                *(uint32_t*)(Oh + o) = pk2(h0, h1);
                *(uint32_t*)(Ol + o) = pk2(g0 - h0, g1 - h1);
            }
        }
    }
}

// ======================= kernel 5: output head (GEMV + clip) =======================
__global__ void head_kernel(const float* __restrict__ Wof, const float* __restrict__ Wob,
                            const float* __restrict__ bof, const float* __restrict__ bob,
                            float* __restrict__ out) {
    int t = blockIdx.x, z = blockIdx.y, tid = threadIdx.x;
    const float* Wo = z ? Wob : Wof;
    const __nv_bfloat16* hi = g_act_hi[z][0] + (size_t)t * HH;
    const __nv_bfloat16* lo = g_act_lo[z][0] + (size_t)t * HH;
    float acc = 0.f;
    for (int n = tid; n < HH; n += 128)
        acc += (__bfloat162float(hi[n]) + __bfloat162float(lo[n])) * Wo[n];
    for (int o = 16; o; o >>= 1) acc += __shfl_down_sync(0xffffffffu, acc, o);
    __shared__ float red[4];
    if ((tid & 31) == 0) red[tid >> 5] = acc;
    __syncthreads();
    if (tid == 0) {
        float v = red[0] + red[1] + red[2] + red[3] + (z ? bob[0] : bof[0]);
        v = fminf(fmaxf(v, 1e-4f), 1.0f - 1e-4f);
        out[(size_t)z * TT + t] = v;
    }
}

// ======================= launch =======================
extern "C" void kernel_launch(void* const* d_in, const int* in_sizes, int n_in,
                              void* d_out, int out_size) {
    (void)in_sizes; (void)n_in; (void)out_size;
    const float* mol  = (const float*)d_in[0];
    const float* sseq = (const float*)d_in[1];
    const float* dseq = (const float*)d_in[2];
    const float* rf   = (const float*)d_in[3];
    const float* sv   = (const float*)d_in[4];
    const float* Wf0 = (const float*)d_in[5],  *Wf1 = (const float*)d_in[6];
    const float* Wf2 = (const float*)d_in[7],  *Wof = (const float*)d_in[8];
    const float* Wb0 = (const float*)d_in[9],  *Wb1 = (const float*)d_in[10];
    const float* Wb2 = (const float*)d_in[11], *Wob = (const float*)d_in[12];
    const float* bf0 = (const float*)d_in[13], *bf1 = (const float*)d_in[14];
    const float* bf2 = (const float*)d_in[15], *bof = (const float*)d_in[16];
    const float* bb0 = (const float*)d_in[17], *bb1 = (const float*)d_in[18];
    const float* bb2 = (const float*)d_in[19], *bob = (const float*)d_in[20];
    float* out = (float*)d_out;

    cudaFuncSetAttribute(gemm_kernel, cudaFuncAttributeMaxDynamicSharedMemorySize, GEMM_SMEM);

    wsplit_kernel<<<16384, 256>>>(Wf1, Wf2, Wb1, Wb2);
    precompute_kernel<<<dim3(HH, 2), 256>>>(Wf0, Wb0, bf0, bb0, mol, sv);
    act0_kernel<<<dim3(HH / 256, TT, 2), 256>>>(sseq, dseq, rf);
    gemm_kernel<<<dim3(HH / 128, TT / 128, 2), 256, GEMM_SMEM>>>(0, bf1, bb1);
    gemm_kernel<<<dim3(HH / 128, TT / 128, 2), 256, GEMM_SMEM>>>(1, bf2, bb2);
    head_kernel<<<dim3(TT, 2), 128>>>(Wof, Wob, bof, bob, out);
}

// round 15
// speedup vs baseline: 1.0094x; 1.0017x over previous
#include <cuda_runtime.h>
#include <cuda_bf16.h>
#include <cstdint>

#define TT   4096
#define HH   2048
#define DIN  12325
#define DBLK 2054

// ======================= scratch (__device__ globals, no cudaMalloc) =======================
__device__ __nv_bfloat16 g_act_hi[2][2][(size_t)TT * HH];
__device__ __nv_bfloat16 g_act_lo[2][2][(size_t)TT * HH];
__device__ __nv_bfloat16 g_w_hi[2][2][(size_t)HH * HH];
__device__ __nv_bfloat16 g_w_lo[2][2][(size_t)HH * HH];
__device__ float g_c[2][HH];
__device__ float g_u[2][5][HH];
__device__ float g_wl[2][HH];
__device__ float g_D[2][6][HH];

// ======================= helpers =======================
__device__ __forceinline__ uint32_t smem_u32(const void* p) {
    uint32_t a;
    asm("{ .reg .u64 t; cvta.to.shared.u64 t, %1; cvt.u32.u64 %0, t; }" : "=r"(a) : "l"(p));
    return a;
}
__device__ __forceinline__ void cp16(uint32_t s, const void* g) {
    asm volatile("cp.async.cg.shared.global [%0], [%1], 16;" :: "r"(s), "l"(g));
}
#define MBAR_INIT(mb, c)   asm volatile("mbarrier.init.shared.b64 [%0], %1;" :: "r"(mb), "r"(c) : "memory")
#define MBAR_ARRIVE(mb)    asm volatile("mbarrier.arrive.shared.b64 _, [%0];" :: "r"(mb) : "memory")
#define CP_MBAR_ARRIVE(mb) asm volatile("cp.async.mbarrier.arrive.noinc.shared.b64 [%0];" :: "r"(mb) : "memory")

#define MBAR_WAIT_PARITY(mbar_smem_addr, phase_parity) do {                                  \
    uint32_t _mbar = (uint32_t)(mbar_smem_addr);                                             \
    uint32_t _parity = (uint32_t)(phase_parity);                                             \
    uint32_t _done;                                                                          \
    asm volatile(                                                                            \
        "{\n\t.reg .pred p;\n\t"                                                             \
        "mbarrier.try_wait.parity.acquire.cta.shared::cta.b64 p, [%1], %2;\n\t"              \
        "selp.b32 %0, 1, 0, p;\n\t}"                                                         \
        : "=r"(_done) : "r"(_mbar), "r"(_parity) : "memory");                                \
    if (!_done) {                                                                            \
        asm volatile(                                                                        \
            "{\n\t.reg .pred P1;\n\t"                                                        \
            "WAIT_LOOP_%=:\n\t"                                                              \
            "mbarrier.try_wait.parity.acquire.cta.shared::cta.b64 P1, [%0], %1, 0x989680;\n\t" \
            "@P1 bra.uni WAIT_DONE_%=;\n\t"                                                  \
            "bra.uni WAIT_LOOP_%=;\n\t"                                                      \
            "WAIT_DONE_%=:\n\t}"                                                             \
            :: "r"(_mbar), "r"(_parity) : "memory");                                         \
    }                                                                                        \
} while (0)

__device__ __forceinline__ void ldsm4(uint32_t* r, uint32_t addr) {
    asm volatile("ldmatrix.sync.aligned.m8n8.x4.shared.b16 {%0,%1,%2,%3}, [%4];"
                 : "=r"(r[0]), "=r"(r[1]), "=r"(r[2]), "=r"(r[3]) : "r"(addr));
}
__device__ __forceinline__ void ldsm2(uint32_t* r, uint32_t addr) {
    asm volatile("ldmatrix.sync.aligned.m8n8.x2.shared.b16 {%0,%1}, [%2];"
                 : "=r"(r[0]), "=r"(r[1]) : "r"(addr));
}
__device__ __forceinline__ void mma16816(float* c, const uint32_t* a, const uint32_t* b) {
    asm volatile("mma.sync.aligned.m16n8k16.row.col.f32.bf16.bf16.f32 "
                 "{%0,%1,%2,%3}, {%4,%5,%6,%7}, {%8,%9}, {%0,%1,%2,%3};"
                 : "+f"(c[0]), "+f"(c[1]), "+f"(c[2]), "+f"(c[3])
                 : "r"(a[0]), "r"(a[1]), "r"(a[2]), "r"(a[3]), "r"(b[0]), "r"(b[1]));
}
__device__ __forceinline__ float gelu_f(float x) {
    return 0.5f * x * (1.0f + erff(x * 0.7071067811865476f));
}
__device__ __forceinline__ uint32_t pk2(float a, float b) {
    __nv_bfloat162 t = __floats2bfloat162_rn(a, b);
    return reinterpret_cast<uint32_t&>(t);
}
__device__ __forceinline__ uint32_t sw128(uint32_t off) {
    return off ^ ((off >> 3) & 0x70u);
}

// ======================= kernel 1: split H x H weights into bf16 hi/lo (float4) =======================
__global__ void wsplit_kernel(const float* __restrict__ Wf1, const float* __restrict__ Wf2,
                              const float* __restrict__ Wb1, const float* __restrict__ Wb2) {
    size_t idx = (size_t)blockIdx.x * 256 + threadIdx.x;   // 4 * 2^20 float4 chunks
    int w = (int)(idx >> 20);
    size_t e4 = idx & ((1u << 20) - 1u);
    const float* src = (w == 0) ? Wf1 : (w == 1) ? Wf2 : (w == 2) ? Wb1 : Wb2;
    float4 v = *(const float4*)(src + e4 * 4);
    float h0 = __bfloat162float(__float2bfloat16_rn(v.x));
    float h1 = __bfloat162float(__float2bfloat16_rn(v.y));
    float h2 = __bfloat162float(__float2bfloat16_rn(v.z));
    float h3 = __bfloat162float(__float2bfloat16_rn(v.w));
    uint2 hv, lv;
    hv.x = pk2(h0, h1); hv.y = pk2(h2, h3);
    lv.x = pk2(v.x - h0, v.y - h1); lv.y = pk2(v.z - h2, v.w - h3);
    *(uint2*)(g_w_hi[w >> 1][w & 1] + e4 * 4) = hv;
    *(uint2*)(g_w_lo[w >> 1][w & 1] + e4 * 4) = lv;
}

// ======================= kernel 2: layer-0 decomposition (one pass over W0) =======================
__global__ void precompute_kernel(const float* __restrict__ Wf0, const float* __restrict__ Wb0,
                                  const float* __restrict__ bf0, const float* __restrict__ bb0,
                                  const float* __restrict__ mol, const float* __restrict__ sv) {
    __shared__ float red[256];
    int h = blockIdx.x, z = blockIdx.y, tid = threadIdx.x;
    const float* W0 = z ? Wb0 : Wf0;
    const float* row = W0 + (size_t)h * DIN;
    float acc[6] = {0.f, 0.f, 0.f, 0.f, 0.f, 0.f};
    for (int m = tid; m < 2048; m += 256) {
        acc[0] += row[m] * mol[m];
#pragma unroll
        for (int j = 0; j < 5; j++)
            acc[1 + j] += row[DBLK * (j + 1) + m] * sv[j * 2048 + m];
    }
#pragma unroll
    for (int a = 0; a < 6; a++) {
        red[tid] = acc[a];
        __syncthreads();
        for (int s = 128; s > 0; s >>= 1) {
            if (tid < s) red[tid] += red[tid + s];
            __syncthreads();
        }
        if (tid == 0) {
            if (a == 0) g_c[z][h] = red[0] + (z ? bb0[h] : bf0[h]);
            else        g_u[z][a - 1][h] = red[0];
        }
        __syncthreads();
    }
    if (tid < 6) {
        float dsum = row[2048 + tid];
#pragma unroll
        for (int j = 0; j < 5; j++) dsum += row[DBLK * (j + 1) + 2048 + tid];
        g_D[z][tid][h] = dsum;
    }
    if (tid == 6) g_wl[z][h] = row[12324];
}

// ======================= kernel 3: layer-0 activation (12 FMA/elem broadcast) =======================
__global__ void act0_kernel(const float* __restrict__ sseq, const float* __restrict__ dseq,
                            const float* __restrict__ rf) {
    int h = blockIdx.x * 256 + threadIdx.x;
    int t = blockIdx.y, z = blockIdx.z;
    float pv = (z == 0) ? ((t == 0) ? 0.5f : rf[t - 1])
                        : ((t == TT - 1) ? 0.5f : rf[t + 1]);
    float v = g_c[z][h] + pv * g_wl[z][h];
#pragma unroll
    for (int j = 0; j < 5; j++) v += __ldg(&sseq[t * 5 + j]) * g_u[z][j][h];
#pragma unroll
    for (int d = 0; d < 6; d++) v += __ldg(&dseq[t * 6 + d]) * g_D[z][d][h];
    float g = gelu_f(v);
    __nv_bfloat16 hi = __float2bfloat16_rn(g);
    __nv_bfloat16 lo = __float2bfloat16_rn(g - __bfloat162float(hi));
    size_t idx = (size_t)t * HH + h;
    g_act_hi[z][0][idx] = hi;
    g_act_lo[z][0][idx] = lo;
}

// ======================= kernel 4: mma.sync split-bf16 GEMM, mbarrier ring pipeline ==========
// CTA tile 128(t) x 128(n), BK=64, 8 warps as 2x4 grid of 64x32 warp tiles.
// 3 HMMA products per k16-step. 3 x 64KB buffers; per-buffer full/free mbarriers;
// no __syncthreads in the mainloop -> warps decouple (skew tolerance ~1 stage).
#define SA_HI 0
#define SA_LO 16384
#define SW_HI 32768
#define SW_LO 49152
#define STAGE_B 65536
#define NSTAGE  3
#define GEMM_SMEM (NSTAGE * STAGE_B + 1024)

__global__ void __launch_bounds__(256, 1)
gemm_kernel(int layer, const float* __restrict__ bias_f, const float* __restrict__ bias_b) {
    extern __shared__ char smem[];
    const uint32_t sbase = smem_u32(smem);
    const uint32_t s0 = (sbase + 1023u) & ~1023u;
    const uint32_t mb_full = s0 + NSTAGE * STAGE_B;      // full[0..2] @ +0,+8,+16
    const uint32_t mb_free = mb_full + 24;               // free[0..2] @ +0,+8,+16

    const int tid = threadIdx.x, lane = tid & 31, warp = tid >> 5;
    const int wm = warp >> 2, wn = warp & 3;          // 2 x 4 warp grid, tile 64x32
    const int n0 = blockIdx.x * 128, t0 = blockIdx.y * 128, z = blockIdx.z;
    const int inp = layer, outp = layer ^ 1;

    const char* Ahi = (const char*)g_act_hi[z][inp];
    const char* Alo = (const char*)g_act_lo[z][inp];
    const char* Whi = (const char*)g_w_hi[z][layer];
    const char* Wlo = (const char*)g_w_lo[z][layer];
    const float* __restrict__ bias = z ? bias_b : bias_f;

    if (tid == 0) {
#pragma unroll
        for (int b = 0; b < NSTAGE; b++) {
            MBAR_INIT(mb_full + b * 8, 256);
            MBAR_INIT(mb_free + b * 8, 256);
        }
    }
    __syncthreads();   // mbarrier init visible before any arrive

    const int lr = tid >> 3, lc = tid & 7;            // loaders: 32 rows x 8 x 16B chunks

    auto load_stage = [&](int kc, int buf) {
        const uint32_t sb = s0 + (uint32_t)buf * STAGE_B;
        const int kb = kc * 128 + lc * 16;            // byte offset within 4096B K-row
#pragma unroll
        for (int p = 0; p < 4; p++) {
            const int r = p * 32 + lr;
            const uint32_t sw = sw128((uint32_t)(r * 128 + lc * 16));
            const size_t ga = (size_t)(t0 + r) * 4096 + kb;
            const size_t gw = (size_t)(n0 + r) * 4096 + kb;
            cp16(sb + SA_HI + sw, Ahi + ga);
            cp16(sb + SA_LO + sw, Alo + ga);
            cp16(sb + SW_HI + sw, Whi + gw);
            cp16(sb + SW_LO + sw, Wlo + gw);
        }
    };

    float acc[4][4][4];
#pragma unroll
    for (int i = 0; i < 4; i++)
#pragma unroll
        for (int j = 0; j < 4; j++)
#pragma unroll
            for (int q = 0; q < 4; q++) acc[i][j][q] = 0.f;

    // preload stages 0, 1 (buffers fresh: no free-wait)
    load_stage(0, 0); CP_MBAR_ARRIVE(mb_full + 0);
    load_stage(1, 1); CP_MBAR_ARRIVE(mb_full + 8);

    int cbuf = 0, cph = 0;        // consumer cursor (full)
    int pbuf = 2, pph = 1;        // producer cursor (free); parity 1 passes immediately on fresh barrier

    for (int kc = 0; kc < 32; ++kc) {
        MBAR_WAIT_PARITY(mb_full + cbuf * 8, cph);    // acquire: stage kc data visible
        const uint32_t sb = s0 + (uint32_t)cbuf * STAGE_B;

#pragma unroll
        for (int ks = 0; ks < 4; ks++) {
            const int acol = ks * 32 + (lane >> 4) * 16;          // A k-bytes
            const int bcol = ks * 32 + ((lane >> 3) & 1) * 16;    // B k-bytes
            uint32_t ah[4][4], bh[4][2], bl[4][2];
#pragma unroll
            for (int i = 0; i < 4; i++) {
                const int row = wm * 64 + i * 16 + (lane & 15);
                ldsm4(ah[i], sb + SA_HI + sw128((uint32_t)(row * 128 + acol)));
            }
#pragma unroll
            for (int j = 0; j < 4; j++) {
                const int row = wn * 32 + j * 8 + (lane & 7);
                const uint32_t sw = sw128((uint32_t)(row * 128 + bcol));
                ldsm2(bh[j], sb + SW_HI + sw);
                ldsm2(bl[j], sb + SW_LO + sw);
            }
#pragma unroll
            for (int i = 0; i < 4; i++)
#pragma unroll
                for (int j = 0; j < 4; j++) mma16816(acc[i][j], ah[i], bh[j]);
#pragma unroll
            for (int i = 0; i < 4; i++)
#pragma unroll
                for (int j = 0; j < 4; j++) mma16816(acc[i][j], ah[i], bl[j]);
            uint32_t al[4][4];
#pragma unroll
            for (int i = 0; i < 4; i++) {
                const int row = wm * 64 + i * 16 + (lane & 15);
                ldsm4(al[i], sb + SA_LO + sw128((uint32_t)(row * 128 + acol)));
            }
            if (ks == 3) MBAR_ARRIVE(mb_free + cbuf * 8);   // last smem read done; release buffer
#pragma unroll
            for (int i = 0; i < 4; i++)
#pragma unroll
                for (int j = 0; j < 4; j++) mma16816(acc[i][j], al[i], bh[j]);
        }
        if (++cbuf == NSTAGE) { cbuf = 0; cph ^= 1; }

        const int s = kc + 2;
        if (s < 32) {
            MBAR_WAIT_PARITY(mb_free + pbuf * 8, pph);      // wait consumers of stage s-3
            load_stage(s, pbuf);
            CP_MBAR_ARRIVE(mb_full + pbuf * 8);
            if (++pbuf == NSTAGE) { pbuf = 0; pph ^= 1; }
        }
    }

    // epilogue: bias + GELU + hi/lo split
    __nv_bfloat16* Oh = g_act_hi[z][outp];
    __nv_bfloat16* Ol = g_act_lo[z][outp];
#pragma unroll
    for (int i = 0; i < 4; i++) {
#pragma unroll
        for (int j = 0; j < 4; j++) {
            const int r0 = t0 + wm * 64 + i * 16 + (lane >> 2);
            const int c  = n0 + wn * 32 + j * 8 + (lane & 3) * 2;
            const float b0 = __ldg(&bias[c]), b1 = __ldg(&bias[c + 1]);
#pragma unroll
            for (int hrow = 0; hrow < 2; hrow++) {
                const float v0 = acc[i][j][hrow * 2 + 0] + b0;
                const float v1 = acc[i][j][hrow * 2 + 1] + b1;
                const float g0 = gelu_f(v0), g1 = gelu_f(v1);
                const float h0 = __bfloat162float(__float2bfloat16_rn(g0));
                const float h1 = __bfloat162float(__float2bfloat16_rn(g1));
                const size_t o = (size_t)(r0 + hrow * 8) * HH + c;
                *(uint32_t*)(Oh + o) = pk2(h0, h1);
                *(uint32_t*)(Ol + o) = pk2(g0 - h0, g1 - h1);
            }
        }
    }
}

// ======================= kernel 5: output head (GEMV + clip) =======================
__global__ void head_kernel(const float* __restrict__ Wof, const float* __restrict__ Wob,
                            const float* __restrict__ bof, const float* __restrict__ bob,
                            float* __restrict__ out) {
    int t = blockIdx.x, z = blockIdx.y, tid = threadIdx.x;
    const float* Wo = z ? Wob : Wof;
    const __nv_bfloat16* hi = g_act_hi[z][0] + (size_t)t * HH;
    const __nv_bfloat16* lo = g_act_lo[z][0] + (size_t)t * HH;
    float acc = 0.f;
    for (int n = tid; n < HH; n += 128)
        acc += (__bfloat162float(hi[n]) + __bfloat162float(lo[n])) * Wo[n];
    for (int o = 16; o; o >>= 1) acc += __shfl_down_sync(0xffffffffu, acc, o);
    __shared__ float red[4];
    if ((tid & 31) == 0) red[tid >> 5] = acc;
    __syncthreads();
    if (tid == 0) {
        float v = red[0] + red[1] + red[2] + red[3] + (z ? bob[0] : bof[0]);
        v = fminf(fmaxf(v, 1e-4f), 1.0f - 1e-4f);
        out[(size_t)z * TT + t] = v;
    }
}

// ======================= launch =======================
extern "C" void kernel_launch(void* const* d_in, const int* in_sizes, int n_in,
                              void* d_out, int out_size) {
    (void)in_sizes; (void)n_in; (void)out_size;
    const float* mol  = (const float*)d_in[0];
    const float* sseq = (const float*)d_in[1];
    const float* dseq = (const float*)d_in[2];
    const float* rf   = (const float*)d_in[3];
    const float* sv   = (const float*)d_in[4];
    const float* Wf0 = (const float*)d_in[5],  *Wf1 = (const float*)d_in[6];
    const float* Wf2 = (const float*)d_in[7],  *Wof = (const float*)d_in[8];
    const float* Wb0 = (const float*)d_in[9],  *Wb1 = (const float*)d_in[10];
    const float* Wb2 = (const float*)d_in[11], *Wob = (const float*)d_in[12];
    const float* bf0 = (const float*)d_in[13], *bf1 = (const float*)d_in[14];
    const float* bf2 = (const float*)d_in[15], *bof = (const float*)d_in[16];
    const float* bb0 = (const float*)d_in[17], *bb1 = (const float*)d_in[18];
    const float* bb2 = (const float*)d_in[19], *bob = (const float*)d_in[20];
    float* out = (float*)d_out;

    cudaFuncSetAttribute(gemm_kernel, cudaFuncAttributeMaxDynamicSharedMemorySize, GEMM_SMEM);

    wsplit_kernel<<<16384, 256>>>(Wf1, Wf2, Wb1, Wb2);
    precompute_kernel<<<dim3(HH, 2), 256>>>(Wf0, Wb0, bf0, bb0, mol, sv);
    act0_kernel<<<dim3(HH / 256, TT, 2), 256>>>(sseq, dseq, rf);
    gemm_kernel<<<dim3(HH / 128, TT / 128, 2), 256, GEMM_SMEM>>>(0, bf1, bb1);
    gemm_kernel<<<dim3(HH / 128, TT / 128, 2), 256, GEMM_SMEM>>>(1, bf2, bb2);
    head_kernel<<<dim3(TT, 2), 128>>>(Wof, Wob, bof, bob, out);
}